// round 6
// baseline (speedup 1.0000x reference)
#include <cuda_runtime.h>
#include <math.h>
#include <float.h>

#define BATCH 8
#define NPTS  4096
#define KN    10
#define NNB   9
#define PI_F  3.14159265358979323846f
#define INF_F __int_as_float(0x7f800000)

// scratch: neighbor indices (B, N, 9)
__device__ int g_knn_idx[BATCH * NPTS * NNB];

// ---------------------------------------------------------------------------
// insert: unsorted top-10, replace the (first) slot equal to running max.
// First-match via parallel prefix-OR tree (depth 4), predicated writes,
// then FMNMX tree to recompute the running max. No serial bool chain.
// ---------------------------------------------------------------------------
#define KNN_INSERT(e, c)                                                     \
    if ((e) < mx) {                                                          \
        bool m0 = (bd[0] == mx), m1 = (bd[1] == mx);                         \
        bool m2 = (bd[2] == mx), m3 = (bd[3] == mx);                         \
        bool m4 = (bd[4] == mx), m5 = (bd[5] == mx);                         \
        bool m6 = (bd[6] == mx), m7 = (bd[7] == mx);                         \
        bool m8 = (bd[8] == mx), m9 = (bd[9] == mx);                         \
        bool o01 = m0 | m1, o23 = m2 | m3, o45 = m4 | m5, o67 = m6 | m7;     \
        bool o03 = o01 | o23, o07 = o03 | o45 | o67;                         \
        bool t0 = m0;                                                        \
        bool t1 = m1 & !m0;                                                  \
        bool t2 = m2 & !o01;                                                 \
        bool t3 = m3 & !(o01 | m2);                                          \
        bool t4 = m4 & !o03;                                                 \
        bool t5 = m5 & !(o03 | m4);                                          \
        bool t6 = m6 & !(o03 | o45);                                         \
        bool t7 = m7 & !(o03 | o45 | m6);                                    \
        bool t8 = m8 & !o07;                                                 \
        bool t9 = m9 & !(o07 | m8);                                          \
        if (t0) { bd[0] = (e); bi[0] = (c); }                                \
        if (t1) { bd[1] = (e); bi[1] = (c); }                                \
        if (t2) { bd[2] = (e); bi[2] = (c); }                                \
        if (t3) { bd[3] = (e); bi[3] = (c); }                                \
        if (t4) { bd[4] = (e); bi[4] = (c); }                                \
        if (t5) { bd[5] = (e); bi[5] = (c); }                                \
        if (t6) { bd[6] = (e); bi[6] = (c); }                                \
        if (t7) { bd[7] = (e); bi[7] = (c); }                                \
        if (t8) { bd[8] = (e); bi[8] = (c); }                                \
        if (t9) { bd[9] = (e); bi[9] = (c); }                                \
        float x0 = fmaxf(bd[0], bd[1]);                                      \
        float x1 = fmaxf(bd[2], bd[3]);                                      \
        float x2 = fmaxf(bd[4], bd[5]);                                      \
        float x3 = fmaxf(bd[6], bd[7]);                                      \
        float x4 = fmaxf(bd[8], bd[9]);                                      \
        mx = fmaxf(fmaxf(fmaxf(x0, x1), fmaxf(x2, x3)), x4);                 \
    }

// ---------------------------------------------------------------------------
// Kernel 1: brute-force kNN. 4 threads per query (1024 candidates each),
// 512-thread blocks, 256 blocks -> ~2 blocks/SM co-resident (32 warps/SM).
// Warp lanes share the candidate stream (broadcast LDS). Exact 4-way merge
// of partial top-10s in SMEM; drop self (= global min).
// ---------------------------------------------------------------------------
__global__ void __launch_bounds__(512) knn_kernel(const float* __restrict__ x)
{
    extern __shared__ float4 spt[];   // 4096 points: {x,y,z, 0.5*|p|^2}

    const int b  = blockIdx.x >> 5;           // 32 blocks per batch
    const int q0 = (blockIdx.x & 31) << 7;    // 128 queries per block
    const float* xb = x + b * 3 * NPTS;
    const int tid = threadIdx.x;

    for (int i = tid; i < NPTS; i += 512) {
        float px = xb[i];
        float py = xb[NPTS + i];
        float pz = xb[2 * NPTS + i];
        spt[i] = make_float4(px, py, pz, 0.5f * (px * px + py * py + pz * pz));
    }
    __syncthreads();

    const int sub = tid >> 7;        // 0..3 : candidate quarter
    const int ql  = tid & 127;       // local query
    const int q   = q0 + ql;
    const int c0  = sub << 10;       // sub * 1024

    const float4 qp = spt[q];
    const float nqx = -qp.x, nqy = -qp.y, nqz = -qp.z;

    float bd[KN];
    int   bi[KN];

    // warmup: 10 fill + 2 singles so the remaining 1012 is divisible by 4
#pragma unroll
    for (int s = 0; s < KN; ++s) {
        float4 p = spt[c0 + s];
        bd[s] = fmaf(nqx, p.x, fmaf(nqy, p.y, fmaf(nqz, p.z, p.w)));
        bi[s] = c0 + s;
    }
    float mx = bd[0];
#pragma unroll
    for (int s = 1; s < KN; ++s) mx = fmaxf(mx, bd[s]);
    {
        float4 pa = spt[c0 + KN];
        float4 pb = spt[c0 + KN + 1];
        float ea = fmaf(nqx, pa.x, fmaf(nqy, pa.y, fmaf(nqz, pa.z, pa.w)));
        float eb = fmaf(nqx, pb.x, fmaf(nqy, pb.y, fmaf(nqz, pb.z, pb.w)));
        KNN_INSERT(ea, c0 + KN);
        KNN_INSERT(eb, c0 + KN + 1);
    }

#pragma unroll 2
    for (int c = c0 + KN + 2; c < c0 + 1024; c += 4) {
        float4 p0 = spt[c];
        float4 p1 = spt[c + 1];
        float4 p2 = spt[c + 2];
        float4 p3 = spt[c + 3];
        float e0 = fmaf(nqx, p0.x, fmaf(nqy, p0.y, fmaf(nqz, p0.z, p0.w)));
        float e1 = fmaf(nqx, p1.x, fmaf(nqy, p1.y, fmaf(nqz, p1.z, p1.w)));
        float e2 = fmaf(nqx, p2.x, fmaf(nqy, p2.y, fmaf(nqz, p2.z, p2.w)));
        float e3 = fmaf(nqx, p3.x, fmaf(nqy, p3.y, fmaf(nqz, p3.z, p3.w)));
        float em = fminf(fminf(e0, e1), fminf(e2, e3));
        if (em < mx) {
            KNN_INSERT(e0, c);
            KNN_INSERT(e1, c + 1);
            KNN_INSERT(e2, c + 2);
            KNN_INSERT(e3, c + 3);
        }
    }

    // --- exact 4-way merge of partial lists (reuse SMEM: 40 KB) ---
    __syncthreads();
    float* pd = (float*)spt;                    // 512*10 floats = 20 KB
    int*   pi = (int*)(pd + 512 * KN);          // 512*10 ints   = 20 KB

    const int base = (ql * 4 + sub) * KN;
#pragma unroll
    for (int s = 0; s < KN; ++s) { pd[base + s] = bd[s]; pi[base + s] = bi[s]; }
    __syncthreads();

    if (sub == 0) {
#pragma unroll 1
        for (int t = 1; t < 4; ++t) {
            const int ob = (ql * 4 + t) * KN;
#pragma unroll
            for (int s = 0; s < KN; ++s) {
                float e = pd[ob + s];
                int   c = pi[ob + s];
                KNN_INSERT(e, c);
            }
        }

        // self = strict global min; emit the other 9 (order arbitrary)
        float mn = bd[0]; int ms = 0;
#pragma unroll
        for (int s = 1; s < KN; ++s) {
            if (bd[s] < mn) { mn = bd[s]; ms = s; }
        }
        int* outp = g_knn_idx + (b * NPTS + q) * NNB;
        int k = 0;
#pragma unroll
        for (int s = 0; s < KN; ++s) {
            if (s != ms) { outp[k] = bi[s]; ++k; }
        }
    }
}

// ---------------------------------------------------------------------------
// Kernel 2: umbrella features + fused MLP (BN folded). One thread per (b,n).
// ---------------------------------------------------------------------------
__global__ void __launch_bounds__(256) feat_kernel(
    const float* __restrict__ x,
    const float* __restrict__ conv1_w,
    const float* __restrict__ bn1_g, const float* __restrict__ bn1_b,
    const float* __restrict__ bn1_m, const float* __restrict__ bn1_v,
    const float* __restrict__ conv2_w, const float* __restrict__ conv2_b,
    const float* __restrict__ bn2_g, const float* __restrict__ bn2_b,
    const float* __restrict__ bn2_m, const float* __restrict__ bn2_v,
    const float* __restrict__ conv3_w, const float* __restrict__ conv3_b,
    float* __restrict__ out)
{
    extern __shared__ float4 spts[];
    __shared__ float W1f[81], W2f[81], W3s[81];
    __shared__ float b1f[9], b2f[9], b3f[9];

    const int b  = blockIdx.x >> 4;
    const int n0 = (blockIdx.x & 15) * 256;
    const int tid = threadIdx.x;

    if (tid < 81) {
        int o = tid / 9;
        float i1 = bn1_g[o] * rsqrtf(bn1_v[o] + 1e-5f);
        float i2 = bn2_g[o] * rsqrtf(bn2_v[o] + 1e-5f);
        W1f[tid] = conv1_w[tid] * i1;
        W2f[tid] = conv2_w[tid] * i2;
        W3s[tid] = conv3_w[tid];
        if (tid < 9) {
            float j1 = bn1_g[tid] * rsqrtf(bn1_v[tid] + 1e-5f);
            float j2 = bn2_g[tid] * rsqrtf(bn2_v[tid] + 1e-5f);
            b1f[tid] = bn1_b[tid] - bn1_m[tid] * j1;
            b2f[tid] = conv2_b[tid] * j2 + bn2_b[tid] - bn2_m[tid] * j2;
            b3f[tid] = conv3_b[tid];
        }
    }

    const float* xb = x + b * 3 * NPTS;
    for (int i = tid; i < NPTS; i += blockDim.x) {
        spts[i] = make_float4(xb[i], xb[NPTS + i], xb[2 * NPTS + i], 0.0f);
    }
    __syncthreads();

    const int n = n0 + tid;
    float4 p = spts[n];

    float gx[NNB], gy[NNB], gz[NNB], ph[NNB];
    const int* nb = g_knn_idx + (b * NPTS + n) * NNB;
#pragma unroll
    for (int j = 0; j < NNB; ++j) {
        float4 pp = spts[nb[j]];
        gx[j] = pp.x - p.x;
        gy[j] = pp.y - p.y;
        gz[j] = pp.z - p.z;
        ph[j] = atan2f(gy[j], gx[j]);
    }

#pragma unroll 1
    for (int a = 1; a < NNB; ++a) {
        float kp = ph[a], kx = gx[a], ky = gy[a], kz = gz[a];
        int t = a - 1;
        while (t >= 0 && ph[t] > kp) {
            ph[t + 1] = ph[t]; gx[t + 1] = gx[t]; gy[t + 1] = gy[t]; gz[t + 1] = gz[t];
            --t;
        }
        ph[t + 1] = kp; gx[t + 1] = kx; gy[t + 1] = ky; gz[t + 1] = kz;
    }

    float acc[9];
#pragma unroll
    for (int o = 0; o < 9; ++o) acc[o] = 0.0f;

    float pos = 1.0f;

#pragma unroll 1
    for (int j = 0; j < NNB; ++j) {
        int jn = (j + 1 == NNB) ? 0 : j + 1;
        float sx = gx[j],  sy = gy[j],  sz = gz[j];
        float rx = gx[jn], ry = gy[jn], rz = gz[jn];

        float cxv = sy * rz - sz * ry;
        float cyv = sz * rx - sx * rz;
        float czv = sx * ry - sy * rx;
        float nrm = sqrtf(cxv * cxv + cyv * cyv + czv * czv);
        float inn = 1.0f / fmaxf(nrm, 1e-10f);
        float ux = cxv * inn, uy = cyv * inn, uz = czv * inn;
        if (j == 0) pos = (ux > 0.0f) ? 1.0f : -1.0f;
        float nx = ux * pos, ny = uy * pos, nz = uz * pos;
        nx = isnan(nx) ? 0.0f : nx;
        ny = isnan(ny) ? 0.0f : ny;
        nz = isnan(nz) ? 0.0f : nz;

        float ccx = (sx + rx) * (1.0f / 3.0f);
        float ccy = (sy + ry) * (1.0f / 3.0f);
        float ccz = (sz + rz) * (1.0f / 3.0f);
        float rho = sqrtf(ccx * ccx + ccy * ccy + ccz * ccz);
        float ct  = ccz / fmaxf(rho, 1e-8f);
        ct = fminf(fmaxf(ct, -1.0f), 1.0f);
        float th  = acosf(ct) * (1.0f / PI_F);
        float phc = atan2f(ccy, ccx) * (1.0f / (2.0f * PI_F)) + 0.5f;

        float f[9] = { ccx, ccy, ccz, rho, th, phc, nx, ny, nz };

        float h1v[9];
#pragma unroll
        for (int o = 0; o < 9; ++o) {
            float a = b1f[o];
#pragma unroll
            for (int c = 0; c < 9; ++c) a = fmaf(W1f[o * 9 + c], f[c], a);
            h1v[o] = fmaxf(a, 0.0f);
        }
        float h2v[9];
#pragma unroll
        for (int o = 0; o < 9; ++o) {
            float a = b2f[o];
#pragma unroll
            for (int c = 0; c < 9; ++c) a = fmaf(W2f[o * 9 + c], h1v[c], a);
            h2v[o] = fmaxf(a, 0.0f);
        }
#pragma unroll
        for (int o = 0; o < 9; ++o) {
            float a = b3f[o];
#pragma unroll
            for (int c = 0; c < 9; ++c) a = fmaf(W3s[o * 9 + c], h2v[c], a);
            acc[o] += a;
        }
    }

    float* ob = out + b * 9 * NPTS + n;
#pragma unroll
    for (int o = 0; o < 9; ++o) ob[o * NPTS] = acc[o];
}

// ---------------------------------------------------------------------------
extern "C" void kernel_launch(void* const* d_in, const int* in_sizes, int n_in,
                              void* d_out, int out_size)
{
    const float* x       = (const float*)d_in[0];
    const float* conv1_w = (const float*)d_in[1];
    const float* bn1_g   = (const float*)d_in[2];
    const float* bn1_b   = (const float*)d_in[3];
    const float* bn1_m   = (const float*)d_in[4];
    const float* bn1_v   = (const float*)d_in[5];
    const float* conv2_w = (const float*)d_in[6];
    const float* conv2_b = (const float*)d_in[7];
    const float* bn2_g   = (const float*)d_in[8];
    const float* bn2_b   = (const float*)d_in[9];
    const float* bn2_m   = (const float*)d_in[10];
    const float* bn2_v   = (const float*)d_in[11];
    const float* conv3_w = (const float*)d_in[12];
    const float* conv3_b = (const float*)d_in[13];
    float* out = (float*)d_out;

    const int smem = NPTS * (int)sizeof(float4);   // 64 KB
    cudaFuncSetAttribute(knn_kernel,  cudaFuncAttributeMaxDynamicSharedMemorySize, smem);
    cudaFuncSetAttribute(feat_kernel, cudaFuncAttributeMaxDynamicSharedMemorySize, smem);

    knn_kernel<<<BATCH * (NPTS / 128), 512, smem>>>(x);
    feat_kernel<<<BATCH * (NPTS / 256), 256, smem>>>(
        x, conv1_w, bn1_g, bn1_b, bn1_m, bn1_v,
        conv2_w, conv2_b, bn2_g, bn2_b, bn2_m, bn2_v,
        conv3_w, conv3_b, out);
}

// round 7
// speedup vs baseline: 1.6744x; 1.6744x over previous
#include <cuda_runtime.h>
#include <math.h>
#include <float.h>

#define BATCH 8
#define NPTS  4096
#define KN    10
#define NNB   9
#define PI_F  3.14159265358979323846f
#define INF_F __int_as_float(0x7f800000)

// scratch: neighbor indices (B, N, 9)
__device__ int g_knn_idx[BATCH * NPTS * NNB];

// ---------------------------------------------------------------------------
// unconditional insert core: replace (first) slot equal to running max.
// parallel prefix-OR first-match + FMNMX tree max recompute.
// caller guarantees (e) < mx.
// ---------------------------------------------------------------------------
#define KNN_INSERT_CORE(e, c)                                                \
    {                                                                        \
        bool m0 = (bd[0] == mx), m1 = (bd[1] == mx);                         \
        bool m2 = (bd[2] == mx), m3 = (bd[3] == mx);                         \
        bool m4 = (bd[4] == mx), m5 = (bd[5] == mx);                         \
        bool m6 = (bd[6] == mx), m7 = (bd[7] == mx);                         \
        bool m8 = (bd[8] == mx), m9 = (bd[9] == mx);                         \
        bool o01 = m0 | m1, o23 = m2 | m3, o45 = m4 | m5, o67 = m6 | m7;     \
        bool o03 = o01 | o23, o07 = o03 | o45 | o67;                         \
        if (m0)                      { bd[0] = (e); bi[0] = (c); }           \
        if (m1 & !m0)                { bd[1] = (e); bi[1] = (c); }           \
        if (m2 & !o01)               { bd[2] = (e); bi[2] = (c); }           \
        if (m3 & !(o01 | m2))        { bd[3] = (e); bi[3] = (c); }           \
        if (m4 & !o03)               { bd[4] = (e); bi[4] = (c); }           \
        if (m5 & !(o03 | m4))        { bd[5] = (e); bi[5] = (c); }           \
        if (m6 & !(o03 | o45))       { bd[6] = (e); bi[6] = (c); }           \
        if (m7 & !(o03 | o45 | m6))  { bd[7] = (e); bi[7] = (c); }           \
        if (m8 & !o07)               { bd[8] = (e); bi[8] = (c); }           \
        if (m9 & !(o07 | m8))        { bd[9] = (e); bi[9] = (c); }           \
        float x0 = fmaxf(bd[0], bd[1]);                                      \
        float x1 = fmaxf(bd[2], bd[3]);                                      \
        float x2 = fmaxf(bd[4], bd[5]);                                      \
        float x3 = fmaxf(bd[6], bd[7]);                                      \
        float x4 = fmaxf(bd[8], bd[9]);                                      \
        mx = fmaxf(fmaxf(fmaxf(x0, x1), fmaxf(x2, x3)), x4);                 \
    }

// guarded single insert
#define KNN_INSERT(e, c) if ((e) < mx) KNN_INSERT_CORE(e, c)

// ---------------------------------------------------------------------------
// Kernel 1: brute-force kNN. 2 threads per query (2048 candidates each),
// 512-thread blocks. Grouped 4-candidate branch; inside a taken group,
// fast-path: insert only the group argmin (guaranteed < mx), knock it out,
// and fall back to full sequential insert only if a 2nd candidate qualifies.
// Exact 2-way merge in SMEM; drop self (= global min).
// ---------------------------------------------------------------------------
__global__ void __launch_bounds__(512) knn_kernel(const float* __restrict__ x)
{
    extern __shared__ float4 spt[];   // 4096 points: {x,y,z, 0.5*|p|^2}

    const int b  = blockIdx.x >> 4;           // 16 blocks per batch
    const int q0 = (blockIdx.x & 15) << 8;    // 256 queries per block
    const float* xb = x + b * 3 * NPTS;
    const int tid = threadIdx.x;

    for (int i = tid; i < NPTS; i += 512) {
        float px = xb[i];
        float py = xb[NPTS + i];
        float pz = xb[2 * NPTS + i];
        spt[i] = make_float4(px, py, pz, 0.5f * (px * px + py * py + pz * pz));
    }
    __syncthreads();

    const int sub = tid >> 8;        // warps 0-7: sub 0, warps 8-15: sub 1
    const int ql  = tid & 255;
    const int q   = q0 + ql;
    const int c0  = sub * (NPTS / 2);

    const float4 qp = spt[q];
    const float nqx = -qp.x, nqy = -qp.y, nqz = -qp.z;

    float bd[KN];
    int   bi[KN];

    // warmup: 10 fill + 2 singles so the remaining 2036 is divisible by 4
#pragma unroll
    for (int s = 0; s < KN; ++s) {
        float4 p = spt[c0 + s];
        bd[s] = fmaf(nqx, p.x, fmaf(nqy, p.y, fmaf(nqz, p.z, p.w)));
        bi[s] = c0 + s;
    }
    float mx = bd[0];
#pragma unroll
    for (int s = 1; s < KN; ++s) mx = fmaxf(mx, bd[s]);
    {
        float4 pa = spt[c0 + KN];
        float4 pb = spt[c0 + KN + 1];
        float ea = fmaf(nqx, pa.x, fmaf(nqy, pa.y, fmaf(nqz, pa.z, pa.w)));
        float eb = fmaf(nqx, pb.x, fmaf(nqy, pb.y, fmaf(nqz, pb.z, pb.w)));
        KNN_INSERT(ea, c0 + KN);
        KNN_INSERT(eb, c0 + KN + 1);
    }

#pragma unroll 2
    for (int c = c0 + KN + 2; c < c0 + NPTS / 2; c += 4) {
        float4 p0 = spt[c];
        float4 p1 = spt[c + 1];
        float4 p2 = spt[c + 2];
        float4 p3 = spt[c + 3];
        float e0 = fmaf(nqx, p0.x, fmaf(nqy, p0.y, fmaf(nqz, p0.z, p0.w)));
        float e1 = fmaf(nqx, p1.x, fmaf(nqy, p1.y, fmaf(nqz, p1.z, p1.w)));
        float e2 = fmaf(nqx, p2.x, fmaf(nqy, p2.y, fmaf(nqz, p2.z, p2.w)));
        float e3 = fmaf(nqx, p3.x, fmaf(nqy, p3.y, fmaf(nqz, p3.z, p3.w)));
        float m01 = fminf(e0, e1);
        float m23 = fminf(e2, e3);
        float em  = fminf(m01, m23);
        if (em < mx) {
            // argmin via the same comparisons (ties -> lower index, harmless)
            bool a01 = (e0 <= e1);
            bool a23 = (e2 <= e3);
            bool a   = (m01 <= m23);
            int  i01 = a01 ? c     : c + 1;
            int  i23 = a23 ? c + 2 : c + 3;
            int  cm  = a ? i01 : i23;
            KNN_INSERT_CORE(em, cm);
            // knock out the inserted candidate
            bool k0 = a & a01, k1 = a & !a01, k2 = !a & a23, k3 = !a & !a23;
            e0 = k0 ? INF_F : e0;
            e1 = k1 ? INF_F : e1;
            e2 = k2 ? INF_F : e2;
            e3 = k3 ? INF_F : e3;
            float em2 = fminf(fminf(e0, e1), fminf(e2, e3));
            if (em2 < mx) {       // rare: a 2nd (3rd/4th) also qualifies
                KNN_INSERT(e0, c);
                KNN_INSERT(e1, c + 1);
                KNN_INSERT(e2, c + 2);
                KNN_INSERT(e3, c + 3);
            }
        }
    }

    // --- exact merge of the two partial lists (reuse SMEM) ---
    __syncthreads();
    float* pd = (float*)spt;                    // 512*10 floats = 20 KB
    int*   pi = (int*)(pd + 512 * KN);          // 512*10 ints   = 20 KB

    const int base = (ql * 2 + sub) * KN;
#pragma unroll
    for (int s = 0; s < KN; ++s) { pd[base + s] = bd[s]; pi[base + s] = bi[s]; }
    __syncthreads();

    if (sub == 0) {
        const int ob = (ql * 2 + 1) * KN;
#pragma unroll
        for (int s = 0; s < KN; ++s) {
            float e = pd[ob + s];
            int   c = pi[ob + s];
            KNN_INSERT(e, c);
        }

        // self = strict global min; emit the other 9 (order arbitrary)
        float mn = bd[0]; int ms = 0;
#pragma unroll
        for (int s = 1; s < KN; ++s) {
            if (bd[s] < mn) { mn = bd[s]; ms = s; }
        }
        int* outp = g_knn_idx + (b * NPTS + q) * NNB;
        int k = 0;
#pragma unroll
        for (int s = 0; s < KN; ++s) {
            if (s != ms) { outp[k] = bi[s]; ++k; }
        }
    }
}

// ---------------------------------------------------------------------------
// Kernel 2: umbrella features + fused MLP (BN folded). One thread per (b,n).
// ---------------------------------------------------------------------------
__global__ void __launch_bounds__(256) feat_kernel(
    const float* __restrict__ x,
    const float* __restrict__ conv1_w,
    const float* __restrict__ bn1_g, const float* __restrict__ bn1_b,
    const float* __restrict__ bn1_m, const float* __restrict__ bn1_v,
    const float* __restrict__ conv2_w, const float* __restrict__ conv2_b,
    const float* __restrict__ bn2_g, const float* __restrict__ bn2_b,
    const float* __restrict__ bn2_m, const float* __restrict__ bn2_v,
    const float* __restrict__ conv3_w, const float* __restrict__ conv3_b,
    float* __restrict__ out)
{
    extern __shared__ float4 spts[];
    __shared__ float W1f[81], W2f[81], W3s[81];
    __shared__ float b1f[9], b2f[9], b3f[9];

    const int b  = blockIdx.x >> 4;
    const int n0 = (blockIdx.x & 15) * 256;
    const int tid = threadIdx.x;

    if (tid < 81) {
        int o = tid / 9;
        float i1 = bn1_g[o] * rsqrtf(bn1_v[o] + 1e-5f);
        float i2 = bn2_g[o] * rsqrtf(bn2_v[o] + 1e-5f);
        W1f[tid] = conv1_w[tid] * i1;
        W2f[tid] = conv2_w[tid] * i2;
        W3s[tid] = conv3_w[tid];
        if (tid < 9) {
            float j1 = bn1_g[tid] * rsqrtf(bn1_v[tid] + 1e-5f);
            float j2 = bn2_g[tid] * rsqrtf(bn2_v[tid] + 1e-5f);
            b1f[tid] = bn1_b[tid] - bn1_m[tid] * j1;
            b2f[tid] = conv2_b[tid] * j2 + bn2_b[tid] - bn2_m[tid] * j2;
            b3f[tid] = conv3_b[tid];
        }
    }

    const float* xb = x + b * 3 * NPTS;
    for (int i = tid; i < NPTS; i += blockDim.x) {
        spts[i] = make_float4(xb[i], xb[NPTS + i], xb[2 * NPTS + i], 0.0f);
    }
    __syncthreads();

    const int n = n0 + tid;
    float4 p = spts[n];

    float gx[NNB], gy[NNB], gz[NNB], ph[NNB];
    const int* nb = g_knn_idx + (b * NPTS + n) * NNB;
#pragma unroll
    for (int j = 0; j < NNB; ++j) {
        float4 pp = spts[nb[j]];
        gx[j] = pp.x - p.x;
        gy[j] = pp.y - p.y;
        gz[j] = pp.z - p.z;
        ph[j] = atan2f(gy[j], gx[j]);
    }

#pragma unroll 1
    for (int a = 1; a < NNB; ++a) {
        float kp = ph[a], kx = gx[a], ky = gy[a], kz = gz[a];
        int t = a - 1;
        while (t >= 0 && ph[t] > kp) {
            ph[t + 1] = ph[t]; gx[t + 1] = gx[t]; gy[t + 1] = gy[t]; gz[t + 1] = gz[t];
            --t;
        }
        ph[t + 1] = kp; gx[t + 1] = kx; gy[t + 1] = ky; gz[t + 1] = kz;
    }

    float acc[9];
#pragma unroll
    for (int o = 0; o < 9; ++o) acc[o] = 0.0f;

    float pos = 1.0f;

#pragma unroll 1
    for (int j = 0; j < NNB; ++j) {
        int jn = (j + 1 == NNB) ? 0 : j + 1;
        float sx = gx[j],  sy = gy[j],  sz = gz[j];
        float rx = gx[jn], ry = gy[jn], rz = gz[jn];

        float cxv = sy * rz - sz * ry;
        float cyv = sz * rx - sx * rz;
        float czv = sx * ry - sy * rx;
        float nrm = sqrtf(cxv * cxv + cyv * cyv + czv * czv);
        float inn = 1.0f / fmaxf(nrm, 1e-10f);
        float ux = cxv * inn, uy = cyv * inn, uz = czv * inn;
        if (j == 0) pos = (ux > 0.0f) ? 1.0f : -1.0f;
        float nx = ux * pos, ny = uy * pos, nz = uz * pos;
        nx = isnan(nx) ? 0.0f : nx;
        ny = isnan(ny) ? 0.0f : ny;
        nz = isnan(nz) ? 0.0f : nz;

        float ccx = (sx + rx) * (1.0f / 3.0f);
        float ccy = (sy + ry) * (1.0f / 3.0f);
        float ccz = (sz + rz) * (1.0f / 3.0f);
        float rho = sqrtf(ccx * ccx + ccy * ccy + ccz * ccz);
        float ct  = ccz / fmaxf(rho, 1e-8f);
        ct = fminf(fmaxf(ct, -1.0f), 1.0f);
        float th  = acosf(ct) * (1.0f / PI_F);
        float phc = atan2f(ccy, ccx) * (1.0f / (2.0f * PI_F)) + 0.5f;

        float f[9] = { ccx, ccy, ccz, rho, th, phc, nx, ny, nz };

        float h1v[9];
#pragma unroll
        for (int o = 0; o < 9; ++o) {
            float a = b1f[o];
#pragma unroll
            for (int c = 0; c < 9; ++c) a = fmaf(W1f[o * 9 + c], f[c], a);
            h1v[o] = fmaxf(a, 0.0f);
        }
        float h2v[9];
#pragma unroll
        for (int o = 0; o < 9; ++o) {
            float a = b2f[o];
#pragma unroll
            for (int c = 0; c < 9; ++c) a = fmaf(W2f[o * 9 + c], h1v[c], a);
            h2v[o] = fmaxf(a, 0.0f);
        }
#pragma unroll
        for (int o = 0; o < 9; ++o) {
            float a = b3f[o];
#pragma unroll
            for (int c = 0; c < 9; ++c) a = fmaf(W3s[o * 9 + c], h2v[c], a);
            acc[o] += a;
        }
    }

    float* ob = out + b * 9 * NPTS + n;
#pragma unroll
    for (int o = 0; o < 9; ++o) ob[o * NPTS] = acc[o];
}

// ---------------------------------------------------------------------------
extern "C" void kernel_launch(void* const* d_in, const int* in_sizes, int n_in,
                              void* d_out, int out_size)
{
    const float* x       = (const float*)d_in[0];
    const float* conv1_w = (const float*)d_in[1];
    const float* bn1_g   = (const float*)d_in[2];
    const float* bn1_b   = (const float*)d_in[3];
    const float* bn1_m   = (const float*)d_in[4];
    const float* bn1_v   = (const float*)d_in[5];
    const float* conv2_w = (const float*)d_in[6];
    const float* conv2_b = (const float*)d_in[7];
    const float* bn2_g   = (const float*)d_in[8];
    const float* bn2_b   = (const float*)d_in[9];
    const float* bn2_m   = (const float*)d_in[10];
    const float* bn2_v   = (const float*)d_in[11];
    const float* conv3_w = (const float*)d_in[12];
    const float* conv3_b = (const float*)d_in[13];
    float* out = (float*)d_out;

    const int smem = NPTS * (int)sizeof(float4);   // 64 KB
    cudaFuncSetAttribute(knn_kernel,  cudaFuncAttributeMaxDynamicSharedMemorySize, smem);
    cudaFuncSetAttribute(feat_kernel, cudaFuncAttributeMaxDynamicSharedMemorySize, smem);

    knn_kernel<<<BATCH * (NPTS / 256), 512, smem>>>(x);
    feat_kernel<<<BATCH * (NPTS / 256), 256, smem>>>(
        x, conv1_w, bn1_g, bn1_b, bn1_m, bn1_v,
        conv2_w, conv2_b, bn2_g, bn2_b, bn2_m, bn2_v,
        conv3_w, conv3_b, out);
}